// round 15
// baseline (speedup 1.0000x reference)
#include <cuda_runtime.h>
#include <cstdint>
#include <math.h>

#define B 32
#define C 128
#define NN 4096
#define HEADS 4
#define DH 32
#define HIDDEN 128
#define QSCALE 0.17677669529663687f   /* 32^-0.5 */
#define GEPS 1e-5f

#define AST 68                 /* u32 stride, A tiles [m][kpair] */
#define BST 68                 /* u32 stride, B tiles [k][npair] */
#define TILE_U32 (128 * AST)   /* 8704 u32 = 34816 B */

// ---------------- scratch ----------------
__device__ uint32_t g_kv[(size_t)B * 2 * 128 * 2048];  // k/v bf16x2 [b][kv][row][npair]
__device__ uint32_t g_q2[(size_t)B * 128 * 2048];      // softmaxed q bf16x2 [b][hidden][npair]
__device__ uint32_t g_M2[B * 128 * 64];                // folded M bf16x2 [b][o][cpair]
__device__ float g_ctx[B * HEADS * DH * DH];
__device__ float g_rsum[B * HIDDEN];
__device__ float g_y[(size_t)B * C * NN];
__device__ float g_sum[B];
__device__ float g_sumsq[B];

__device__ __forceinline__ uint32_t pack_bf16(float lo, float hi) {
    uint32_t r;
    asm("cvt.rn.bf16x2.f32 %0, %1, %2;" : "=r"(r) : "f"(hi), "f"(lo));
    return r;
}

__device__ __forceinline__ void mma_bf16(float* d, const uint32_t* a, const uint32_t* b) {
    asm("mma.sync.aligned.m16n8k16.row.col.f32.bf16.bf16.f32 "
        "{%0,%1,%2,%3}, {%4,%5,%6,%7}, {%8,%9}, {%0,%1,%2,%3};"
        : "+f"(d[0]), "+f"(d[1]), "+f"(d[2]), "+f"(d[3])
        : "r"(a[0]), "r"(a[1]), "r"(a[2]), "r"(a[3]), "r"(b[0]), "r"(b[1]));
}

__device__ __forceinline__ uint32_t smem_u32(const void* p) {
    uint32_t a;
    asm("{ .reg .u64 t; cvta.to.shared.u64 t, %1; cvt.u32.u64 %0, t; }" : "=r"(a) : "l"(p));
    return a;
}
__device__ __forceinline__ void ldsm4(uint32_t* r, uint32_t a) {
    asm volatile("ldmatrix.sync.aligned.m8n8.x4.shared.b16 {%0,%1,%2,%3}, [%4];"
        : "=r"(r[0]), "=r"(r[1]), "=r"(r[2]), "=r"(r[3]) : "r"(a));
}
__device__ __forceinline__ void ldsm4t(uint32_t* r, uint32_t a) {
    asm volatile("ldmatrix.sync.aligned.m8n8.x4.trans.shared.b16 {%0,%1,%2,%3}, [%4];"
        : "=r"(r[0]), "=r"(r[1]), "=r"(r[2]), "=r"(r[3]) : "r"(a));
}

// ---------------- K0: zero accumulators ----------------
__global__ void __launch_bounds__(256) k0_zero() {
    int gid = blockIdx.x * 256 + threadIdx.x;
    float4 z = make_float4(0.f, 0.f, 0.f, 0.f);
    if (gid < 32768) ((float4*)g_ctx)[gid] = z;
    if (gid < 1024)  ((float4*)g_rsum)[gid] = z;
    if (gid < 32) { g_sum[gid] = 0.f; g_sumsq[gid] = 0.f; }
}

// ---------------- ldmatrix GEMM pieces ----------------
struct Frag { float d[4][4][4]; };

// A rows (row-major fp32, stride 128) -> [m][kpair] bf16x2
__device__ __forceinline__ void stage_rm128(uint32_t* s, const float* __restrict__ src, int tid) {
    int r = tid & 127, half = tid >> 7;
    const float4* sp = (const float4*)(src + (size_t)r * 128 + half * 64);
    uint32_t* dst = s + r * AST + half * 32;
#pragma unroll
    for (int j = 0; j < 8; j++) {
        float4 w0 = sp[2 * j], w1 = sp[2 * j + 1];
        uint4 p;
        p.x = pack_bf16(w0.x, w0.y); p.y = pack_bf16(w0.z, w0.w);
        p.z = pack_bf16(w1.x, w1.y); p.w = pack_bf16(w1.z, w1.w);
        *(uint4*)(dst + j * 4) = p;
    }
}
// x tile (rows k, stride NN fp32) -> [k][npair] bf16x2 (no transpose!)
__device__ __forceinline__ void stage_x(uint32_t* s, const float* __restrict__ xb, int tid) {
    int k = tid >> 1, half = tid & 1;
    const float4* sp = (const float4*)(xb + (size_t)k * NN + half * 64);
    uint32_t* dst = s + k * BST + half * 32;
#pragma unroll
    for (int j = 0; j < 8; j++) {
        float4 w0 = sp[2 * j], w1 = sp[2 * j + 1];
        uint4 p;
        p.x = pack_bf16(w0.x, w0.y); p.y = pack_bf16(w0.z, w0.w);
        p.z = pack_bf16(w1.x, w1.y); p.w = pack_bf16(w1.z, w1.w);
        *(uint4*)(dst + j * 4) = p;
    }
}
// prepacked u32 tile copy (rows 128, srcStride u32) -> stride-AST tile
__device__ __forceinline__ void copy_tile(uint32_t* s, const uint32_t* __restrict__ src,
                                          int srcStride, int tid) {
    int r = tid & 127, half = tid >> 7;
    const uint4* sp = (const uint4*)(src + (size_t)r * srcStride + half * 32);
    uint4* dst = (uint4*)(s + r * AST + half * 32);
#pragma unroll
    for (int j = 0; j < 8; j++) dst[j] = sp[j];
}

__device__ __forceinline__ void ldsm_bases(
    uint32_t* aB, uint32_t* bB, const uint32_t* sA, const uint32_t* sB,
    int lane, int mbase, int nbase)
{
    int jj = lane >> 3, rr = lane & 7;
    uint32_t sa = smem_u32(sA), sb = smem_u32(sB);
#pragma unroll
    for (int mt = 0; mt < 4; mt++)
        aB[mt] = sa + (((mbase + mt * 16 + (jj & 1) * 8 + rr) * AST + (jj >> 1) * 4) << 2);
#pragma unroll
    for (int g = 0; g < 2; g++)
        bB[g] = sb + ((((jj & 1) * 8 + rr) * BST + ((nbase + g * 16 + (jj >> 1) * 8) >> 1)) << 2);
}

__device__ __forceinline__ void gemm_ldsm(Frag& f, const uint32_t* aB, const uint32_t* bB) {
#pragma unroll
    for (int mt = 0; mt < 4; mt++)
#pragma unroll
        for (int nt = 0; nt < 4; nt++)
#pragma unroll
            for (int r = 0; r < 4; r++) f.d[mt][nt][r] = 0.f;
#pragma unroll
    for (int ks = 0; ks < 8; ks++) {
        uint32_t a[4][4], bb[2][4];
#pragma unroll
        for (int g = 0; g < 2; g++) ldsm4t(bb[g], bB[g] + ks * (16 * BST * 4));
#pragma unroll
        for (int mt = 0; mt < 4; mt++) ldsm4(a[mt], aB[mt] + ks * 32);
#pragma unroll
        for (int mt = 0; mt < 4; mt++)
#pragma unroll
            for (int nt = 0; nt < 4; nt++)
                mma_bf16(f.d[mt][nt], a[mt], &bb[nt >> 1][(nt & 1) * 2]);
    }
}

// ---------------- K1a: k,v projections ----------------
// grid (32 ncol, 32 b), 256 threads
__global__ void __launch_bounds__(256) k1_kv(
    const float* __restrict__ x,
    const float* __restrict__ Wk,
    const float* __restrict__ Wv)
{
    extern __shared__ uint32_t dsm[];
    uint32_t* sW = dsm;
    uint32_t* sX = dsm + TILE_U32;

    const int b  = blockIdx.y;
    const int n0 = blockIdx.x * 128;
    const int tid = threadIdx.x;
    const int lane = tid & 31, wid = tid >> 5;
    const int mbase = (wid >> 2) * 64, nbase = (wid & 3) * 32;
    const int gid = lane >> 2, tig = lane & 3;

    stage_x(sX, x + (size_t)b * C * NN + n0, tid);

    uint32_t aB[4], bB[2];
    ldsm_bases(aB, bB, sW, sX, lane, mbase, nbase);

#pragma unroll 1
    for (int kv = 0; kv < 2; kv++) {
        if (kv) __syncthreads();
        stage_rm128(sW, kv ? Wv : Wk, tid);
        __syncthreads();

        Frag f;
        gemm_ldsm(f, aB, bB);

        uint32_t* outp = g_kv + ((size_t)(b * 2 + kv) * 128) * 2048 + (n0 >> 1);
#pragma unroll
        for (int mt = 0; mt < 4; mt++) {
#pragma unroll
            for (int nt = 0; nt < 4; nt++) {
                int row = mbase + mt * 16 + gid;
                int npair = ((nbase + nt * 8) >> 1) + tig;
                outp[(size_t)row * 2048 + npair] =
                    pack_bf16(f.d[mt][nt][0], f.d[mt][nt][1]);
                outp[(size_t)(row + 8) * 2048 + npair] =
                    pack_bf16(f.d[mt][nt][2], f.d[mt][nt][3]);
            }
        }
    }
}

// ---------------- K1b: q projection + softmax -> g_q2 [hidden][npair] ----------------
__global__ void __launch_bounds__(256) k1_q(
    const float* __restrict__ x,
    const float* __restrict__ Wq)
{
    extern __shared__ uint32_t dsm[];
    uint32_t* sW = dsm;
    uint32_t* sX = dsm + TILE_U32;
    float* stage = (float*)dsm;   // aliased [128][132] after gemm

    const int b  = blockIdx.y;
    const int n0 = blockIdx.x * 128;
    const int tid = threadIdx.x;
    const int lane = tid & 31, wid = tid >> 5;
    const int mbase = (wid >> 2) * 64, nbase = (wid & 3) * 32;
    const int gid = lane >> 2, tig = lane & 3;

    stage_x(sX, x + (size_t)b * C * NN + n0, tid);
    stage_rm128(sW, Wq, tid);

    uint32_t aB[4], bB[2];
    ldsm_bases(aB, bB, sW, sX, lane, mbase, nbase);
    __syncthreads();

    Frag f;
    gemm_ldsm(f, aB, bB);

    __syncthreads();
#pragma unroll
    for (int mt = 0; mt < 4; mt++) {
#pragma unroll
        for (int nt = 0; nt < 4; nt++) {
            int row = mbase + mt * 16 + gid;
            int col = nbase + nt * 8 + tig * 2;
            *(float2*)&stage[row * 132 + col] =
                make_float2(f.d[mt][nt][0], f.d[mt][nt][1]);
            *(float2*)&stage[(row + 8) * 132 + col] =
                make_float2(f.d[mt][nt][2], f.d[mt][nt][3]);
        }
    }
    __syncthreads();

    // softmax over d per (h, col); write bf16x2 n-pairs to g_q2
    {
        const int cp = tid & 63;          // n-pair within tile
        const int h = tid >> 6;           // head
        const int col0 = 2 * cp, col1 = col0 + 1;
        float sum0 = 0.f, sum1 = 0.f;
#pragma unroll
        for (int dd = 0; dd < 32; dd++) {
            float* p = &stage[(h * 32 + dd) * 132 + col0];
            float e0 = __expf(p[0]);
            float e1 = __expf(p[1]);
            p[0] = e0; p[1] = e1;
            sum0 += e0; sum1 += e1;
        }
        float inv0 = QSCALE / sum0, inv1 = QSCALE / sum1;
        uint32_t* outq = g_q2 + (size_t)b * 128 * 2048 + (n0 >> 1) + cp;
#pragma unroll
        for (int dd = 0; dd < 32; dd++) {
            const float* p = &stage[(h * 32 + dd) * 132 + col0];
            outq[(size_t)(h * 32 + dd) * 2048] = pack_bf16(p[0] * inv0, p[1] * inv1);
        }
    }
}

// ---------------- K2: bf16 mma partial ctx = exp(k) @ v^T + rowsum ----------------
#define K2PAD 34
#define K2HALF (128 * K2PAD)
__global__ void __launch_bounds__(256) k2_ctx()
{
    __shared__ uint32_t s2[2 * K2HALF];
    uint32_t* sKb = s2;
    uint32_t* sVb = s2 + K2HALF;

    const int bh = blockIdx.y;
    const int b = bh >> 2, h = bh & 3;
    const int cbp = blockIdx.x * 256;
    const uint32_t* kb32 = g_kv + ((size_t)(b * 2 + 0) * 128 + h * 32) * 2048 + cbp;
    const uint32_t* vb32 = g_kv + ((size_t)(b * 2 + 1) * 128 + h * 32) * 2048 + cbp;

    const int tid = threadIdx.x;
    const int lane = tid & 31, w = tid >> 5;
    const int gid = lane >> 2, tig = lane & 3;

    const int row = tid >> 3;
    const int t   = tid & 7;

    float c[2][4][4];
#pragma unroll
    for (int mt = 0; mt < 2; mt++)
#pragma unroll
        for (int nt = 0; nt < 4; nt++)
#pragma unroll
            for (int r = 0; r < 4; r++) c[mt][nt][r] = 0.f;
    float lsum = 0.f;

#pragma unroll 1
    for (int half = 0; half < 2; half++) {
        const int pb = half * 128;
        __syncthreads();
#pragma unroll
        for (int j = 0; j < 8; j++) {
            int pr = 2 * t + 16 * j;
            uint2 kk = *(const uint2*)&kb32[(size_t)row * 2048 + pb + pr];
            float a0 = __uint_as_float(kk.x << 16);
            float a1 = __uint_as_float(kk.x & 0xffff0000u);
            float a2 = __uint_as_float(kk.y << 16);
            float a3 = __uint_as_float(kk.y & 0xffff0000u);
            float e0 = __expf(a0), e1 = __expf(a1);
            float e2 = __expf(a2), e3 = __expf(a3);
            lsum += e0 + e1 + e2 + e3;
            sKb[pr * K2PAD + row] = pack_bf16(e0, e1);
            sKb[(pr + 1) * K2PAD + row] = pack_bf16(e2, e3);
            uint2 vv = *(const uint2*)&vb32[(size_t)row * 2048 + pb + pr];
            sVb[pr * K2PAD + row] = vv.x;
            sVb[(pr + 1) * K2PAD + row] = vv.y;
        }
        __syncthreads();
#pragma unroll
        for (int kt = 0; kt < 2; kt++) {
            const int base = w * 16 + kt * 8;
            uint32_t a[2][4], bf[4][2];
#pragma unroll
            for (int mt = 0; mt < 2; mt++) {
                int r2 = mt * 16 + gid;
                a[mt][0] = sKb[(base + tig) * K2PAD + r2];
                a[mt][1] = sKb[(base + tig) * K2PAD + r2 + 8];
                a[mt][2] = sKb[(base + tig + 4) * K2PAD + r2];
                a[mt][3] = sKb[(base + tig + 4) * K2PAD + r2 + 8];
            }
#pragma unroll
            for (int nt = 0; nt < 4; nt++) {
                int col = nt * 8 + gid;
                bf[nt][0] = sVb[(base + tig) * K2PAD + col];
                bf[nt][1] = sVb[(base + tig + 4) * K2PAD + col];
            }
#pragma unroll
            for (int mt = 0; mt < 2; mt++)
#pragma unroll
                for (int nt = 0; nt < 4; nt++)
                    mma_bf16(c[mt][nt], a[mt], bf[nt]);
        }
    }

#pragma unroll
    for (int o = 4; o; o >>= 1) lsum += __shfl_xor_sync(0xffffffffu, lsum, o);
    if ((tid & 7) == 0)
        atomicAdd(&g_rsum[b * HIDDEN + h * 32 + row], lsum);

    __syncthreads();
    float* pbuf = (float*)s2;
#pragma unroll
    for (int mt = 0; mt < 2; mt++) {
#pragma unroll
        for (int nt = 0; nt < 4; nt++) {
            int r2 = mt * 16 + gid;
            int col = nt * 8 + tig * 2;
            pbuf[(w * 32 + r2) * K2PAD + col]     = c[mt][nt][0];
            pbuf[(w * 32 + r2) * K2PAD + col + 1] = c[mt][nt][1];
            pbuf[(w * 32 + r2 + 8) * K2PAD + col]     = c[mt][nt][2];
            pbuf[(w * 32 + r2 + 8) * K2PAD + col + 1] = c[mt][nt][3];
        }
    }
    __syncthreads();
    {
        const int d = tid >> 3;
        const int e0 = (tid & 7) * 4;
        float s0 = 0.f, s1 = 0.f, s2v = 0.f, s3 = 0.f;
#pragma unroll
        for (int ww = 0; ww < 8; ww++) {
            const float* p = &pbuf[(ww * 32 + d) * K2PAD + e0];
            s0 += p[0]; s1 += p[1]; s2v += p[2]; s3 += p[3];
        }
        float* cp = &g_ctx[((size_t)bh * 32 + d) * 32 + e0];
        atomicAdd(cp + 0, s0);
        atomicAdd(cp + 1, s1);
        atomicAdd(cp + 2, s2v);
        atomicAdd(cp + 3, s3);
    }
}

// ---------------- K3: M_b = Wo @ blockdiag(ctx^T / rsum) -> g_M2 [o][cpair] ----------------
__global__ void __launch_bounds__(256) k3_fold(const float* __restrict__ Wo)
{
    const int b = blockIdx.y;
    const int og = blockIdx.x * 4;
    __shared__ float sctx[HEADS * DH * DH];
    __shared__ float sinv[HIDDEN];
    const int tid = threadIdx.x;
#pragma unroll
    for (int rr = 0; rr < 4; rr++) {
        int idx = tid + rr * 256;
        *(float4*)&sctx[idx * 4] = *(const float4*)&g_ctx[(size_t)b * 4096 + idx * 4];
    }
    if (tid < 128) sinv[tid] = 1.0f / g_rsum[b * HIDDEN + tid];
    __syncthreads();

    const int o = og + (tid >> 6);
    const int col0 = (tid & 63) * 2;
    const int h = col0 >> 5;
    const int d0 = col0 & 31;

    float wo[32];
#pragma unroll
    for (int q4 = 0; q4 < 8; q4++) {
        float4 t = *(const float4*)&Wo[o * 128 + h * 32 + q4 * 4];
        wo[q4 * 4 + 0] = t.x; wo[q4 * 4 + 1] = t.y;
        wo[q4 * 4 + 2] = t.z; wo[q4 * 4 + 3] = t.w;
    }
    float4 a0 = make_float4(0.f, 0.f, 0.f, 0.f);
    float4 a1 = make_float4(0.f, 0.f, 0.f, 0.f);
#pragma unroll
    for (int q4 = 0; q4 < 8; q4++) {
        float4 c0v = *(const float4*)&sctx[(h * 32 + d0) * 32 + q4 * 4];
        float4 c1v = *(const float4*)&sctx[(h * 32 + d0 + 1) * 32 + q4 * 4];
        a0.x += wo[q4 * 4 + 0] * c0v.x; a0.y += wo[q4 * 4 + 1] * c0v.y;
        a0.z += wo[q4 * 4 + 2] * c0v.z; a0.w += wo[q4 * 4 + 3] * c0v.w;
        a1.x += wo[q4 * 4 + 0] * c1v.x; a1.y += wo[q4 * 4 + 1] * c1v.y;
        a1.z += wo[q4 * 4 + 2] * c1v.z; a1.w += wo[q4 * 4 + 3] * c1v.w;
    }
    float s0 = (a0.x + a0.y) + (a0.z + a0.w);
    float s1 = (a1.x + a1.y) + (a1.z + a1.w);
    g_M2[b * 8192 + o * 64 + (col0 >> 1)] =
        pack_bf16(s0 * sinv[col0], s1 * sinv[col0 + 1]);
}

// ---------------- K4: y = M_b @ softq + bo, ldmatrix mainloop ----------------
__global__ void __launch_bounds__(256) k4_out(const float* __restrict__ bo)
{
    extern __shared__ uint32_t dsm[];
    uint32_t* sA = dsm;
    uint32_t* sB = dsm + TILE_U32;
    __shared__ float redS[8], redQ[8];

    const int b  = blockIdx.y;
    const int n0 = blockIdx.x * 128;
    const int tid = threadIdx.x;
    const int lane = tid & 31, wid = tid >> 5;
    const int mbase = (wid >> 2) * 64, nbase = (wid & 3) * 32;
    const int gid = lane >> 2, tig = lane & 3;

    copy_tile(sA, g_M2 + b * 8192, 64, tid);
    copy_tile(sB, g_q2 + (size_t)b * 128 * 2048 + (n0 >> 1), 2048, tid);

    uint32_t aB[4], bB[2];
    ldsm_bases(aB, bB, sA, sB, lane, mbase, nbase);
    __syncthreads();

    Frag f;
    gemm_ldsm(f, aB, bB);

    float* outp = g_y + (size_t)b * C * NN + n0;
    float lsum = 0.f, lsq = 0.f;
#pragma unroll
    for (int mt = 0; mt < 4; mt++) {
        int row = mbase + mt * 16 + gid;
        float bb0 = bo[row], bb8 = bo[row + 8];
#pragma unroll
        for (int nt = 0; nt < 4; nt++) {
            int col = nbase + nt * 8 + tig * 2;
            float v0 = f.d[mt][nt][0] + bb0, v1 = f.d[mt][nt][1] + bb0;
            float v2 = f.d[mt][nt][2] + bb8, v3 = f.d[mt][nt][3] + bb8;
            *(float2*)&outp[(size_t)row * NN + col] = make_float2(v0, v1);
            *(float2*)&outp[(size_t)(row + 8) * NN + col] = make_float2(v2, v3);
            lsum += v0 + v1 + v2 + v3;
            lsq  += v0 * v0 + v1 * v1 + v2 * v2 + v3 * v3;
        }
    }
#pragma unroll
    for (int o = 16; o; o >>= 1) {
        lsum += __shfl_xor_sync(0xffffffffu, lsum, o);
        lsq  += __shfl_xor_sync(0xffffffffu, lsq,  o);
    }
    if (lane == 0) { redS[wid] = lsum; redQ[wid] = lsq; }
    __syncthreads();
    if (tid == 0) {
        float s = 0.f, q = 0.f;
#pragma unroll
        for (int i = 0; i < 8; i++) { s += redS[i]; q += redQ[i]; }
        atomicAdd(&g_sum[b], s);
        atomicAdd(&g_sumsq[b], q);
    }
}

// ---------------- K5: GroupNorm, float4 ----------------
__global__ void __launch_bounds__(256) k5_norm(
    const float* __restrict__ gn_w, const float* __restrict__ gn_b,
    float* __restrict__ out)
{
    int i4 = blockIdx.x * 256 + threadIdx.x;
    int b = i4 >> 17;
    int c = (i4 >> 10) & 127;
    const float cn = (float)(C * NN);
    float mu = g_sum[b] / cn;
    float var = g_sumsq[b] / cn - mu * mu;
    float is = rsqrtf(var + GEPS);
    float w = gn_w[c] * is, bb = gn_b[c] - mu * w;
    float4 v = *(const float4*)&g_y[(size_t)i4 * 4];
    v.x = v.x * w + bb; v.y = v.y * w + bb;
    v.z = v.z * w + bb; v.w = v.w * w + bb;
    *(float4*)&out[(size_t)i4 * 4] = v;
}

// ---------------- launch (fork-join: k2,k3 overlap k1_q) ----------------
extern "C" void kernel_launch(void* const* d_in, const int* in_sizes, int n_in,
                              void* d_out, int out_size)
{
    const float* x  = (const float*)d_in[0];
    const float* Wq = (const float*)d_in[1];
    const float* Wk = (const float*)d_in[2];
    const float* Wv = (const float*)d_in[3];
    const float* Wo = (const float*)d_in[4];
    const float* bo = (const float*)d_in[5];
    const float* gw = (const float*)d_in[6];
    const float* gb = (const float*)d_in[7];
    float* out = (float*)d_out;

    static int inited = 0;
    static cudaStream_t s2;
    static cudaEvent_t ev1, ev2;
    const int GEMM_SMEM = 2 * TILE_U32 * 4;   // 69632 B (>= 67584 q-stage alias)
    if (!inited) {
        cudaFuncSetAttribute(k1_kv, cudaFuncAttributeMaxDynamicSharedMemorySize, GEMM_SMEM);
        cudaFuncSetAttribute(k1_q,  cudaFuncAttributeMaxDynamicSharedMemorySize, GEMM_SMEM);
        cudaFuncSetAttribute(k4_out, cudaFuncAttributeMaxDynamicSharedMemorySize, GEMM_SMEM);
        cudaStreamCreateWithFlags(&s2, cudaStreamNonBlocking);
        cudaEventCreateWithFlags(&ev1, cudaEventDisableTiming);
        cudaEventCreateWithFlags(&ev2, cudaEventDisableTiming);
        inited = 1;
    }

    k0_zero<<<132, 256>>>();
    k1_kv<<<dim3(32, 32), 256, GEMM_SMEM>>>(x, Wk, Wv);
    cudaEventRecord(ev1, 0);

    cudaStreamWaitEvent(s2, ev1, 0);
    k2_ctx<<<dim3(8, 128), 256, 0, s2>>>();
    k3_fold<<<dim3(32, 32), 256, 0, s2>>>(Wo);
    cudaEventRecord(ev2, s2);

    k1_q<<<dim3(32, 32), 256, GEMM_SMEM>>>(x, Wq);

    cudaStreamWaitEvent(0, ev2, 0);
    k4_out<<<dim3(32, 32), 256, GEMM_SMEM>>>(bo);
    k5_norm<<<16384, 256>>>(gw, gb, out);
}